// round 1
// baseline (speedup 1.0000x reference)
#include <cuda_runtime.h>
#include <cuda_bf16.h>
#include <math.h>

// ---------------- problem constants ----------------
#define BATCH 2
#define TSEQ  2048
#define NROW  (BATCH * TSEQ)   // 4096
#define DMODEL 768
#define NHEAD 12
#define HDIM  64
#define NLAYER 6
#define FFDIM (4 * DMODEL)     // 3072
#define VOCAB 50257
#define LNEPS 1e-5f

// ---------------- scratch (device globals; no allocations allowed) ----------
__device__ float g_x[NROW * DMODEL];
__device__ float g_h[NROW * DMODEL];
__device__ float g_q[NROW * DMODEL];
__device__ float g_k[NROW * DMODEL];
__device__ float g_v[NROW * DMODEL];
__device__ float g_a[NROW * DMODEL];
__device__ float g_f[NROW * FFDIM];

// ---------------- embedding: x = wte[idx] + wpe[t] ----------------
__global__ void embed_kernel(const int* __restrict__ idx,
                             const float* __restrict__ wte,
                             const float* __restrict__ wpe,
                             float* __restrict__ x) {
    int row = blockIdx.x;              // 0..NROW-1
    int t   = row % TSEQ;
    int tok = idx[row];
    const float* we = wte + (size_t)tok * DMODEL;
    const float* wp = wpe + (size_t)t   * DMODEL;
    float* xo = x + (size_t)row * DMODEL;
    for (int d = threadIdx.x; d < DMODEL; d += blockDim.x)
        xo[d] = we[d] + wp[d];
}

// ---------------- layernorm (one block per row) ----------------
__global__ void ln_kernel(const float* __restrict__ x,
                          const float* __restrict__ g,
                          const float* __restrict__ b,
                          float* __restrict__ out) {
    int row = blockIdx.x;
    const float* xr = x + (size_t)row * DMODEL;
    float* orow = out + (size_t)row * DMODEL;
    int tid = threadIdx.x;

    float s = 0.f, sq = 0.f;
    for (int d = tid; d < DMODEL; d += blockDim.x) {
        float v = xr[d];
        s += v; sq += v * v;
    }
    __shared__ float shs[256], shq[256];
    shs[tid] = s; shq[tid] = sq;
    __syncthreads();
    for (int o = 128; o > 0; o >>= 1) {
        if (tid < o) { shs[tid] += shs[tid + o]; shq[tid] += shq[tid + o]; }
        __syncthreads();
    }
    float mu  = shs[0] * (1.0f / DMODEL);
    float var = shq[0] * (1.0f / DMODEL) - mu * mu;
    float rs  = rsqrtf(var + LNEPS);
    for (int d = tid; d < DMODEL; d += blockDim.x)
        orow[d] = (xr[d] - mu) * rs * g[d] + b[d];
}

// ---------------- tiled SGEMM with epilogue flags ----------------
// C[M,N] = epi( A[M,K] @ B )  where B is [K,N] (NN) or [N,K] (NT / TRANSB)
// epilogue: (+bias[col]) -> (gelu) -> (+res[row,col])
#define BM 128
#define BN 128
#define BK 16
#define TM 8
#define TN 8

__device__ __forceinline__ float gelu_exact(float v) {
    return 0.5f * v * (1.0f + erff(v * 0.70710678118654752f));
}

template<bool TRANSB, bool BIAS, bool GELU, bool RES>
__global__ __launch_bounds__(256)
void gemm_kernel(const float* __restrict__ A, const float* __restrict__ B,
                 const float* __restrict__ bias, const float* __restrict__ res,
                 float* __restrict__ C, int M, int N, int K) {
    __shared__ float As[BK][BM];
    __shared__ float Bs[BK][BN];

    int bm = blockIdx.y * BM;
    int bn = blockIdx.x * BN;
    int tid = threadIdx.x;
    int tx = tid & 15;        // 0..15 -> N
    int ty = tid >> 4;        // 0..15 -> M

    float acc[TM][TN];
    #pragma unroll
    for (int i = 0; i < TM; i++)
        #pragma unroll
        for (int j = 0; j < TN; j++) acc[i][j] = 0.f;

    int arow = tid >> 2;          // 0..63
    int acol = (tid & 3) << 2;    // 0,4,8,12

    for (int k0 = 0; k0 < K; k0 += BK) {
        // ---- load A tile (BM x BK), stored K-major ----
        #pragma unroll
        for (int i = 0; i < 2; i++) {
            int r = arow + i * 64;
            float4 v = *(const float4*)(A + (size_t)(bm + r) * K + k0 + acol);
            As[acol + 0][r] = v.x; As[acol + 1][r] = v.y;
            As[acol + 2][r] = v.z; As[acol + 3][r] = v.w;
        }
        // ---- load B tile ----
        if (TRANSB) {
            // B is [N,K] row-major; tile rows are N-values
            #pragma unroll
            for (int i = 0; i < 2; i++) {
                int r = arow + i * 64;       // n within tile
                int n = bn + r;
                float4 v = make_float4(0.f, 0.f, 0.f, 0.f);
                if (n < N) v = *(const float4*)(B + (size_t)n * K + k0 + acol);
                Bs[acol + 0][r] = v.x; Bs[acol + 1][r] = v.y;
                Bs[acol + 2][r] = v.z; Bs[acol + 3][r] = v.w;
            }
        } else {
            // B is [K,N] row-major
            #pragma unroll
            for (int i = 0; i < 2; i++) {
                int r = (tid >> 5) + i * 8;   // k within tile
                int c = (tid & 31) << 2;      // n within tile
                int n = bn + c;
                float4 v = make_float4(0.f, 0.f, 0.f, 0.f);
                if (n < N) v = *(const float4*)(B + (size_t)(k0 + r) * N + n);
                *(float4*)&Bs[r][c] = v;
            }
        }
        __syncthreads();

        #pragma unroll
        for (int k = 0; k < BK; k++) {
            float a[TM], bb[TN];
            #pragma unroll
            for (int i = 0; i < TM; i++) a[i] = As[k][ty * TM + i];
            #pragma unroll
            for (int j = 0; j < TN; j++) bb[j] = Bs[k][tx * TN + j];
            #pragma unroll
            for (int i = 0; i < TM; i++)
                #pragma unroll
                for (int j = 0; j < TN; j++)
                    acc[i][j] = fmaf(a[i], bb[j], acc[i][j]);
        }
        __syncthreads();
    }

    // ---- epilogue ----
    #pragma unroll
    for (int i = 0; i < TM; i++) {
        int row = bm + ty * TM + i;
        #pragma unroll
        for (int j = 0; j < TN; j++) {
            int col = bn + tx * TN + j;
            if (col < N) {
                float v = acc[i][j];
                if (BIAS) v += bias[col];
                if (GELU) v = gelu_exact(v);
                if (RES)  v += res[(size_t)row * N + col];
                C[(size_t)row * N + col] = v;
            }
        }
    }
}

// ---------------- fused causal attention (streaming softmax) ----------------
// grid: (TSEQ/16, NHEAD, BATCH), block 128; each warp owns 4 query rows
#define ATQ 16
#define ATK 32
__global__ __launch_bounds__(128)
void attn_kernel(const float* __restrict__ Q, const float* __restrict__ K,
                 const float* __restrict__ V, float* __restrict__ O) {
    int qb   = blockIdx.x * ATQ;
    int h    = blockIdx.y;
    int b    = blockIdx.z;
    int warp = threadIdx.x >> 5;
    int lane = threadIdx.x & 31;

    __shared__ float Ks[ATK][HDIM];
    __shared__ float Vs[ATK][HDIM];

    const size_t base = (size_t)b * TSEQ * DMODEL + (size_t)h * HDIM;
    const float* Kg = K + base;
    const float* Vg = V + base;

    float qreg[4][2], m[4], l[4], acc[4][2];
    #pragma unroll
    for (int r = 0; r < 4; r++) {
        int qi = qb + warp * 4 + r;
        qreg[r][0] = Q[base + (size_t)qi * DMODEL + lane];
        qreg[r][1] = Q[base + (size_t)qi * DMODEL + 32 + lane];
        m[r] = -1e30f; l[r] = 0.f;
        acc[r][0] = 0.f; acc[r][1] = 0.f;
    }

    const int qmax = qb + ATQ - 1;
    for (int kt = 0; kt <= qmax; kt += ATK) {
        if (kt) __syncthreads();
        // cooperative load of K/V tile: 512 float4 each, 128 threads
        for (int t = threadIdx.x; t < ATK * HDIM / 4; t += 128) {
            int row = t >> 4;
            int c4  = t & 15;
            ((float4*)Ks)[t] = *(const float4*)(Kg + (size_t)(kt + row) * DMODEL + c4 * 4);
            ((float4*)Vs)[t] = *(const float4*)(Vg + (size_t)(kt + row) * DMODEL + c4 * 4);
        }
        __syncthreads();

        int kend = qmax - kt + 1;
        if (kend > ATK) kend = ATK;
        for (int kk = 0; kk < kend; kk++) {
            int ki = kt + kk;
            float k0 = Ks[kk][lane], k1 = Ks[kk][lane + 32];
            float v0 = Vs[kk][lane], v1 = Vs[kk][lane + 32];
            #pragma unroll
            for (int r = 0; r < 4; r++) {
                int qi = qb + warp * 4 + r;
                if (ki <= qi) {
                    float d = qreg[r][0] * k0 + qreg[r][1] * k1;
                    d += __shfl_xor_sync(0xffffffffu, d, 16);
                    d += __shfl_xor_sync(0xffffffffu, d, 8);
                    d += __shfl_xor_sync(0xffffffffu, d, 4);
                    d += __shfl_xor_sync(0xffffffffu, d, 2);
                    d += __shfl_xor_sync(0xffffffffu, d, 1);
                    float s  = d * 0.125f;            // 1/sqrt(64)
                    float nm = fmaxf(m[r], s);
                    float cf = __expf(s - nm);
                    float f  = __expf(m[r] - nm);
                    l[r] = l[r] * f + cf;
                    acc[r][0] = acc[r][0] * f + cf * v0;
                    acc[r][1] = acc[r][1] * f + cf * v1;
                    m[r] = nm;
                }
            }
        }
    }

    #pragma unroll
    for (int r = 0; r < 4; r++) {
        int qi = qb + warp * 4 + r;
        float inv = 1.0f / l[r];
        O[base + (size_t)qi * DMODEL + lane]      = acc[r][0] * inv;
        O[base + (size_t)qi * DMODEL + 32 + lane] = acc[r][1] * inv;
    }
}

// ---------------- host-side orchestration ----------------
static inline void launch_gemm_nn(const float* A, const float* B, float* C,
                                  int M, int N, int K) {
    dim3 g((N + BN - 1) / BN, M / BM);
    gemm_kernel<false, false, false, false><<<g, 256>>>(A, B, nullptr, nullptr, C, M, N, K);
}
static inline void launch_gemm_nn_res(const float* A, const float* B,
                                      const float* res, float* C,
                                      int M, int N, int K) {
    dim3 g((N + BN - 1) / BN, M / BM);
    gemm_kernel<false, false, false, true><<<g, 256>>>(A, B, nullptr, res, C, M, N, K);
}
static inline void launch_gemm_nn_bias_gelu(const float* A, const float* B,
                                            const float* bias, float* C,
                                            int M, int N, int K) {
    dim3 g((N + BN - 1) / BN, M / BM);
    gemm_kernel<false, true, true, false><<<g, 256>>>(A, B, bias, nullptr, C, M, N, K);
}
static inline void launch_gemm_nn_bias_res(const float* A, const float* B,
                                           const float* bias, const float* res,
                                           float* C, int M, int N, int K) {
    dim3 g((N + BN - 1) / BN, M / BM);
    gemm_kernel<false, true, false, true><<<g, 256>>>(A, B, bias, res, C, M, N, K);
}
static inline void launch_gemm_nt(const float* A, const float* B, float* C,
                                  int M, int N, int K) {
    dim3 g((N + BN - 1) / BN, M / BM);
    gemm_kernel<true, false, false, false><<<g, 256>>>(A, B, nullptr, nullptr, C, M, N, K);
}

extern "C" void kernel_launch(void* const* d_in, const int* in_sizes, int n_in,
                              void* d_out, int out_size) {
    // metadata order
    const int*   idx   = (const int*)  d_in[0];
    const float* wte   = (const float*)d_in[1];
    const float* wpe   = (const float*)d_in[2];
    const float* Wq    = (const float*)d_in[3];
    const float* Wk    = (const float*)d_in[4];
    const float* Wv    = (const float*)d_in[5];
    const float* Wo    = (const float*)d_in[6];
    const float* ln1_g = (const float*)d_in[7];
    const float* ln1_b = (const float*)d_in[8];
    const float* ln2_g = (const float*)d_in[9];
    const float* ln2_b = (const float*)d_in[10];
    const float* W1    = (const float*)d_in[11];
    const float* b1    = (const float*)d_in[12];
    const float* W2    = (const float*)d_in[13];
    const float* b2    = (const float*)d_in[14];
    const float* lnf_g = (const float*)d_in[15];
    const float* lnf_b = (const float*)d_in[16];
    float* out = (float*)d_out;

    float *x, *h, *q, *k, *v, *a, *f;
    cudaGetSymbolAddress((void**)&x, g_x);
    cudaGetSymbolAddress((void**)&h, g_h);
    cudaGetSymbolAddress((void**)&q, g_q);
    cudaGetSymbolAddress((void**)&k, g_k);
    cudaGetSymbolAddress((void**)&v, g_v);
    cudaGetSymbolAddress((void**)&a, g_a);
    cudaGetSymbolAddress((void**)&f, g_f);

    // embedding
    embed_kernel<<<NROW, 256>>>(idx, wte, wpe, x);

    for (int l = 0; l < NLAYER; l++) {
        const float* wq = Wq + (size_t)l * DMODEL * DMODEL;
        const float* wk = Wk + (size_t)l * DMODEL * DMODEL;
        const float* wv = Wv + (size_t)l * DMODEL * DMODEL;
        const float* wo = Wo + (size_t)l * DMODEL * DMODEL;
        const float* w1 = W1 + (size_t)l * DMODEL * FFDIM;
        const float* w2 = W2 + (size_t)l * FFDIM * DMODEL;
        const float* bb1 = b1 + (size_t)l * FFDIM;
        const float* bb2 = b2 + (size_t)l * DMODEL;

        // ln1
        ln_kernel<<<NROW, 256>>>(x, ln1_g + (size_t)l * DMODEL,
                                 ln1_b + (size_t)l * DMODEL, h);
        // q,k,v projections
        launch_gemm_nn(h, wq, q, NROW, DMODEL, DMODEL);
        launch_gemm_nn(h, wk, k, NROW, DMODEL, DMODEL);
        launch_gemm_nn(h, wv, v, NROW, DMODEL, DMODEL);
        // attention
        {
            dim3 g(TSEQ / ATQ, NHEAD, BATCH);
            attn_kernel<<<g, 128>>>(q, k, v, a);
        }
        // output projection + residual
        launch_gemm_nn_res(a, wo, x, x, NROW, DMODEL, DMODEL);
        // ln2
        ln_kernel<<<NROW, 256>>>(x, ln2_g + (size_t)l * DMODEL,
                                 ln2_b + (size_t)l * DMODEL, h);
        // mlp
        launch_gemm_nn_bias_gelu(h, w1, bb1, f, NROW, FFDIM, DMODEL);
        launch_gemm_nn_bias_res(f, w2, bb2, x, x, NROW, DMODEL, FFDIM);
    }

    // final LN + tied lm_head (x @ wte^T)
    ln_kernel<<<NROW, 256>>>(x, lnf_g, lnf_b, h);
    launch_gemm_nt(h, wte, out, NROW, VOCAB, DMODEL);

    (void)in_sizes; (void)n_in; (void)out_size;
}

// round 3
// speedup vs baseline: 1.4911x; 1.4911x over previous
#include <cuda_runtime.h>
#include <cuda_bf16.h>
#include <math.h>
#include <stdint.h>

// ---------------- problem constants ----------------
#define BATCH 2
#define TSEQ  2048
#define NROW  (BATCH * TSEQ)   // 4096
#define DMODEL 768
#define NHEAD 12
#define HDIM  64
#define NLAYER 6
#define FFDIM (4 * DMODEL)     // 3072
#define VOCAB 50257
#define LNEPS 1e-5f

// ---------------- scratch (device globals; no allocations allowed) ----------
__device__ float g_x[NROW * DMODEL];
__device__ float g_h[NROW * DMODEL];
__device__ float g_q[NROW * DMODEL];
__device__ float g_k[NROW * DMODEL];
__device__ float g_v[NROW * DMODEL];
__device__ float g_a[NROW * DMODEL];
__device__ float g_f[NROW * FFDIM];

// ---------------- embedding: x = wte[idx] + wpe[t] ----------------
__global__ void embed_kernel(const int* __restrict__ idx,
                             const float* __restrict__ wte,
                             const float* __restrict__ wpe,
                             float* __restrict__ x) {
    int row = blockIdx.x;
    int t   = row % TSEQ;
    int tok = idx[row];
    const float* we = wte + (size_t)tok * DMODEL;
    const float* wp = wpe + (size_t)t   * DMODEL;
    float* xo = x + (size_t)row * DMODEL;
    for (int d = threadIdx.x; d < DMODEL; d += blockDim.x)
        xo[d] = we[d] + wp[d];
}

// ---------------- layernorm (one block per row) ----------------
__global__ void ln_kernel(const float* __restrict__ x,
                          const float* __restrict__ g,
                          const float* __restrict__ b,
                          float* __restrict__ out) {
    int row = blockIdx.x;
    const float* xr = x + (size_t)row * DMODEL;
    float* orow = out + (size_t)row * DMODEL;
    int tid = threadIdx.x;

    float s = 0.f, sq = 0.f;
    for (int d = tid; d < DMODEL; d += blockDim.x) {
        float v = xr[d];
        s += v; sq += v * v;
    }
    __shared__ float shs[256], shq[256];
    shs[tid] = s; shq[tid] = sq;
    __syncthreads();
    for (int o = 128; o > 0; o >>= 1) {
        if (tid < o) { shs[tid] += shs[tid + o]; shq[tid] += shq[tid + o]; }
        __syncthreads();
    }
    float mu  = shs[0] * (1.0f / DMODEL);
    float var = shq[0] * (1.0f / DMODEL) - mu * mu;
    float rs  = rsqrtf(var + LNEPS);
    for (int d = tid; d < DMODEL; d += blockDim.x)
        orow[d] = (xr[d] - mu) * rs * g[d] + b[d];
}

// ---------------- tf32 tensor-core GEMM (mma.sync m16n8k8) ----------------
// C[M,N] = epi( A[M,K] @ B )  B is [K,N] (NN) or [N,K] (NT / TRANSB)
// Tiles: 128x128x32, 256 threads (8 warps: 4 in M x 2 in N), warp tile 32x64.

__device__ __forceinline__ uint32_t f2tf32(float f) {
    uint32_t r;
    asm("cvt.rna.tf32.f32 %0, %1;" : "=r"(r) : "f"(f));
    return r;
}

__device__ __forceinline__ void mma_tf32(float c[4], const uint32_t a[4],
                                         const uint32_t b[2]) {
    asm volatile(
        "mma.sync.aligned.m16n8k8.row.col.f32.tf32.tf32.f32 "
        "{%0,%1,%2,%3}, {%4,%5,%6,%7}, {%8,%9}, {%0,%1,%2,%3};"
        : "+f"(c[0]), "+f"(c[1]), "+f"(c[2]), "+f"(c[3])
        : "r"(a[0]), "r"(a[1]), "r"(a[2]), "r"(a[3]), "r"(b[0]), "r"(b[1]));
}

__device__ __forceinline__ float gelu_exact(float v) {
    return 0.5f * v * (1.0f + erff(v * 0.70710678118654752f));
}

#define GBM 128
#define GBN 128
#define GBK 32
#define APAD 36   // [m][k] row stride (k-dim padded 32->36)
#define BPAD 132  // [k][n] row stride (n-dim padded 128->132)

template<bool TRANSB, bool BIAS, bool GELU, bool RES>
__global__ __launch_bounds__(256)
void mma_gemm(const float* __restrict__ A, const float* __restrict__ B,
              const float* __restrict__ bias, const float* __restrict__ res,
              float* __restrict__ C, int M, int N, int K) {
    __shared__ uint32_t As[GBM * APAD];                       // [m][k]
    __shared__ uint32_t Bs[TRANSB ? GBN * APAD : GBK * BPAD]; // NT:[n][k] NN:[k][n]

    const int bm   = blockIdx.y * GBM;
    const int bn   = blockIdx.x * GBN;
    const int tid  = threadIdx.x;
    const int lane = tid & 31;
    const int wid  = tid >> 5;
    const int warpM = wid & 3;     // 0..3 -> m offset *32
    const int warpN = wid >> 2;    // 0..1 -> n offset *64
    const int grp  = lane >> 2;    // 0..7
    const int tig  = lane & 3;     // 0..3

    float acc[2][8][4];
    #pragma unroll
    for (int mi = 0; mi < 2; mi++)
        #pragma unroll
        for (int ni = 0; ni < 8; ni++)
            #pragma unroll
            for (int r = 0; r < 4; r++) acc[mi][ni][r] = 0.f;

    float4 pa[4], pb[4];

    // ---- global load of one (kt) tile into registers ----
    auto load_tiles = [&](int kt) {
        #pragma unroll
        for (int i = 0; i < 4; i++) {
            int idx  = tid + i * 256;           // 0..1023
            int row  = idx >> 3;                // 0..127 (m)
            int col4 = idx & 7;                 // 0..7   (k/4)
            pa[i] = *(const float4*)(A + (size_t)(bm + row) * K + kt + col4 * 4);
        }
        if (TRANSB) {
            #pragma unroll
            for (int i = 0; i < 4; i++) {
                int idx  = tid + i * 256;
                int nrow = idx >> 3;            // 0..127 (n)
                int col4 = idx & 7;             // 0..7   (k/4)
                int n = bn + nrow;
                float4 v = make_float4(0.f, 0.f, 0.f, 0.f);
                if (n < N) v = *(const float4*)(B + (size_t)n * K + kt + col4 * 4);
                pb[i] = v;
            }
        } else {
            #pragma unroll
            for (int i = 0; i < 4; i++) {
                int idx  = tid + i * 256;
                int row  = idx >> 5;            // 0..31  (k)
                int col4 = idx & 31;            // 0..31  (n/4)
                pb[i] = *(const float4*)(B + (size_t)(kt + row) * N + bn + col4 * 4);
            }
        }
    };

    auto store_tiles = [&]() {
        #pragma unroll
        for (int i = 0; i < 4; i++) {
            int idx  = tid + i * 256;
            int row  = idx >> 3;
            int col4 = idx & 7;
            uint32_t* p = &As[row * APAD + col4 * 4];
            p[0] = f2tf32(pa[i].x); p[1] = f2tf32(pa[i].y);
            p[2] = f2tf32(pa[i].z); p[3] = f2tf32(pa[i].w);
        }
        if (TRANSB) {
            #pragma unroll
            for (int i = 0; i < 4; i++) {
                int idx  = tid + i * 256;
                int nrow = idx >> 3;
                int col4 = idx & 7;
                uint32_t* p = &Bs[nrow * APAD + col4 * 4];
                p[0] = f2tf32(pb[i].x); p[1] = f2tf32(pb[i].y);
                p[2] = f2tf32(pb[i].z); p[3] = f2tf32(pb[i].w);
            }
        } else {
            #pragma unroll
            for (int i = 0; i < 4; i++) {
                int idx  = tid + i * 256;
                int row  = idx >> 5;
                int col4 = idx & 31;
                uint32_t* p = &Bs[row * BPAD + col4 * 4];
                p[0] = f2tf32(pb[i].x); p[1] = f2tf32(pb[i].y);
                p[2] = f2tf32(pb[i].z); p[3] = f2tf32(pb[i].w);
            }
        }
    };

    load_tiles(0);

    for (int kt = 0; kt < K; kt += GBK) {
        store_tiles();
        __syncthreads();
        if (kt + GBK < K) load_tiles(kt + GBK);

        #pragma unroll
        for (int ks = 0; ks < 4; ks++) {
            const int k8 = ks * 8;
            uint32_t af[2][4];
            #pragma unroll
            for (int mi = 0; mi < 2; mi++) {
                int rm = warpM * 32 + mi * 16;
                af[mi][0] = As[(rm + grp)     * APAD + k8 + tig];
                af[mi][1] = As[(rm + 8 + grp) * APAD + k8 + tig];
                af[mi][2] = As[(rm + grp)     * APAD + k8 + 4 + tig];
                af[mi][3] = As[(rm + 8 + grp) * APAD + k8 + 4 + tig];
            }
            uint32_t bf[8][2];
            #pragma unroll
            for (int ni = 0; ni < 8; ni++) {
                int cn = warpN * 64 + ni * 8 + grp;
                if (TRANSB) {
                    bf[ni][0] = Bs[cn * APAD + k8 + tig];
                    bf[ni][1] = Bs[cn * APAD + k8 + 4 + tig];
                } else {
                    bf[ni][0] = Bs[(k8 + tig)     * BPAD + cn];
                    bf[ni][1] = Bs[(k8 + 4 + tig) * BPAD + cn];
                }
            }
            #pragma unroll
            for (int mi = 0; mi < 2; mi++)
                #pragma unroll
                for (int ni = 0; ni < 8; ni++)
                    mma_tf32(acc[mi][ni], af[mi], bf[ni]);
        }
        __syncthreads();
    }

    // ---- epilogue ----
    #pragma unroll
    for (int mi = 0; mi < 2; mi++) {
        #pragma unroll
        for (int ni = 0; ni < 8; ni++) {
            int row0 = bm + warpM * 32 + mi * 16 + grp;
            int col0 = bn + warpN * 64 + ni * 8 + 2 * tig;
            #pragma unroll
            for (int r = 0; r < 4; r++) {
                int row = row0 + (r >= 2 ? 8 : 0);
                int col = col0 + (r & 1);
                if (col < N) {
                    float v = acc[mi][ni][r];
                    if (BIAS) v += bias[col];
                    if (GELU) v = gelu_exact(v);
                    if (RES)  v += res[(size_t)row * N + col];
                    C[(size_t)row * N + col] = v;
                }
            }
        }
    }
}

// ---------------- fused causal attention (streaming softmax) ----------------
#define ATQ 16
#define ATK 32
__global__ __launch_bounds__(128)
void attn_kernel(const float* __restrict__ Q, const float* __restrict__ K,
                 const float* __restrict__ V, float* __restrict__ O) {
    int qb   = blockIdx.x * ATQ;
    int h    = blockIdx.y;
    int b    = blockIdx.z;
    int warp = threadIdx.x >> 5;
    int lane = threadIdx.x & 31;

    __shared__ float Ks[ATK][HDIM];
    __shared__ float Vs[ATK][HDIM];

    const size_t base = (size_t)b * TSEQ * DMODEL + (size_t)h * HDIM;
    const float* Kg = K + base;
    const float* Vg = V + base;

    float qreg[4][2], m[4], l[4], acc[4][2];
    #pragma unroll
    for (int r = 0; r < 4; r++) {
        int qi = qb + warp * 4 + r;
        qreg[r][0] = Q[base + (size_t)qi * DMODEL + lane];
        qreg[r][1] = Q[base + (size_t)qi * DMODEL + 32 + lane];
        m[r] = -1e30f; l[r] = 0.f;
        acc[r][0] = 0.f; acc[r][1] = 0.f;
    }

    const int qmax = qb + ATQ - 1;
    for (int kt = 0; kt <= qmax; kt += ATK) {
        if (kt) __syncthreads();
        for (int t = threadIdx.x; t < ATK * HDIM / 4; t += 128) {
            int row = t >> 4;
            int c4  = t & 15;
            ((float4*)Ks)[t] = *(const float4*)(Kg + (size_t)(kt + row) * DMODEL + c4 * 4);
            ((float4*)Vs)[t] = *(const float4*)(Vg + (size_t)(kt + row) * DMODEL + c4 * 4);
        }
        __syncthreads();

        int kend = qmax - kt + 1;
        if (kend > ATK) kend = ATK;
        for (int kk = 0; kk < kend; kk++) {
            int ki = kt + kk;
            float k0 = Ks[kk][lane], k1 = Ks[kk][lane + 32];
            float v0 = Vs[kk][lane], v1 = Vs[kk][lane + 32];
            #pragma unroll
            for (int r = 0; r < 4; r++) {
                int qi = qb + warp * 4 + r;
                if (ki <= qi) {
                    float d = qreg[r][0] * k0 + qreg[r][1] * k1;
                    d += __shfl_xor_sync(0xffffffffu, d, 16);
                    d += __shfl_xor_sync(0xffffffffu, d, 8);
                    d += __shfl_xor_sync(0xffffffffu, d, 4);
                    d += __shfl_xor_sync(0xffffffffu, d, 2);
                    d += __shfl_xor_sync(0xffffffffu, d, 1);
                    float s  = d * 0.125f;
                    float nm = fmaxf(m[r], s);
                    float cf = __expf(s - nm);
                    float f  = __expf(m[r] - nm);
                    l[r] = l[r] * f + cf;
                    acc[r][0] = acc[r][0] * f + cf * v0;
                    acc[r][1] = acc[r][1] * f + cf * v1;
                    m[r] = nm;
                }
            }
        }
    }

    #pragma unroll
    for (int r = 0; r < 4; r++) {
        int qi = qb + warp * 4 + r;
        float inv = 1.0f / l[r];
        O[base + (size_t)qi * DMODEL + lane]      = acc[r][0] * inv;
        O[base + (size_t)qi * DMODEL + 32 + lane] = acc[r][1] * inv;
    }
}

// ---------------- launch helpers ----------------
static inline dim3 gemm_grid(int M, int N) {
    return dim3((N + GBN - 1) / GBN, M / GBM);
}

extern "C" void kernel_launch(void* const* d_in, const int* in_sizes, int n_in,
                              void* d_out, int out_size) {
    const int*   idx   = (const int*)  d_in[0];
    const float* wte   = (const float*)d_in[1];
    const float* wpe   = (const float*)d_in[2];
    const float* Wq    = (const float*)d_in[3];
    const float* Wk    = (const float*)d_in[4];
    const float* Wv    = (const float*)d_in[5];
    const float* Wo    = (const float*)d_in[6];
    const float* ln1_g = (const float*)d_in[7];
    const float* ln1_b = (const float*)d_in[8];
    const float* ln2_g = (const float*)d_in[9];
    const float* ln2_b = (const float*)d_in[10];
    const float* W1    = (const float*)d_in[11];
    const float* b1    = (const float*)d_in[12];
    const float* W2    = (const float*)d_in[13];
    const float* b2    = (const float*)d_in[14];
    const float* lnf_g = (const float*)d_in[15];
    const float* lnf_b = (const float*)d_in[16];
    float* out = (float*)d_out;

    float *x, *h, *q, *k, *v, *a, *f;
    cudaGetSymbolAddress((void**)&x, g_x);
    cudaGetSymbolAddress((void**)&h, g_h);
    cudaGetSymbolAddress((void**)&q, g_q);
    cudaGetSymbolAddress((void**)&k, g_k);
    cudaGetSymbolAddress((void**)&v, g_v);
    cudaGetSymbolAddress((void**)&a, g_a);
    cudaGetSymbolAddress((void**)&f, g_f);

    embed_kernel<<<NROW, 256>>>(idx, wte, wpe, x);

    for (int l = 0; l < NLAYER; l++) {
        const float* wq = Wq + (size_t)l * DMODEL * DMODEL;
        const float* wk = Wk + (size_t)l * DMODEL * DMODEL;
        const float* wv = Wv + (size_t)l * DMODEL * DMODEL;
        const float* wo = Wo + (size_t)l * DMODEL * DMODEL;
        const float* w1 = W1 + (size_t)l * DMODEL * FFDIM;
        const float* w2 = W2 + (size_t)l * FFDIM * DMODEL;
        const float* bb1 = b1 + (size_t)l * FFDIM;
        const float* bb2 = b2 + (size_t)l * DMODEL;

        ln_kernel<<<NROW, 256>>>(x, ln1_g + (size_t)l * DMODEL,
                                 ln1_b + (size_t)l * DMODEL, h);

        mma_gemm<false,false,false,false><<<gemm_grid(NROW, DMODEL), 256>>>(
            h, wq, nullptr, nullptr, q, NROW, DMODEL, DMODEL);
        mma_gemm<false,false,false,false><<<gemm_grid(NROW, DMODEL), 256>>>(
            h, wk, nullptr, nullptr, k, NROW, DMODEL, DMODEL);
        mma_gemm<false,false,false,false><<<gemm_grid(NROW, DMODEL), 256>>>(
            h, wv, nullptr, nullptr, v, NROW, DMODEL, DMODEL);

        {
            dim3 g(TSEQ / ATQ, NHEAD, BATCH);
            attn_kernel<<<g, 128>>>(q, k, v, a);
        }

        mma_gemm<false,false,false,true><<<gemm_grid(NROW, DMODEL), 256>>>(
            a, wo, nullptr, x, x, NROW, DMODEL, DMODEL);

        ln_kernel<<<NROW, 256>>>(x, ln2_g + (size_t)l * DMODEL,
                                 ln2_b + (size_t)l * DMODEL, h);

        mma_gemm<false,true,true,false><<<gemm_grid(NROW, FFDIM), 256>>>(
            h, w1, bb1, nullptr, f, NROW, FFDIM, DMODEL);
        mma_gemm<false,true,false,true><<<gemm_grid(NROW, DMODEL), 256>>>(
            f, w2, bb2, x, x, NROW, DMODEL, FFDIM);
    }

    ln_kernel<<<NROW, 256>>>(x, lnf_g, lnf_b, h);
    mma_gemm<true,false,false,false><<<gemm_grid(NROW, VOCAB), 256>>>(
        h, wte, nullptr, nullptr, out, NROW, VOCAB, DMODEL);

    (void)in_sizes; (void)n_in; (void)out_size;
}

// round 5
// speedup vs baseline: 1.7785x; 1.1928x over previous
#include <cuda_runtime.h>
#include <cuda_fp16.h>
#include <math.h>
#include <stdint.h>

// ---------------- problem constants ----------------
#define BATCH 2
#define TSEQ  2048
#define NROW  (BATCH * TSEQ)   // 4096
#define DMODEL 768
#define NHEAD 12
#define HDIM  64
#define NLAYER 6
#define FFDIM (4 * DMODEL)     // 3072
#define QKVN  (3 * DMODEL)     // 2304
#define VOCAB 50257
#define LNEPS 1e-5f

// ---------------- scratch (device globals; no allocations) ----------------
__device__ float  g_x[NROW * DMODEL];          // residual stream (fp32)
__device__ __half g_h16[NROW * DMODEL];        // LN output (GEMM A)
__device__ __half g_a16[NROW * DMODEL];        // attention out (GEMM A)
__device__ __half g_f16[NROW * FFDIM];         // GELU out (GEMM A)
__device__ __half g_qkv[NROW * QKVN];          // fused qkv output

// fp16 transposed weights [N,K]
__device__ __half g_wqkv[NLAYER * QKVN * DMODEL];     // [2304,768] per layer
__device__ __half g_wot [NLAYER * DMODEL * DMODEL];   // [768,768]
__device__ __half g_w1t [NLAYER * FFDIM * DMODEL];    // [3072,768]
__device__ __half g_w2t [NLAYER * DMODEL * FFDIM];    // [768,3072]
__device__ __half g_wteh[VOCAB * DMODEL];             // [50257,768] (already NT)

// ---------------- weight conversion ----------------
// transpose+convert: src fp32 [K,N] row-major -> dst fp16 [N,K]
__global__ void convT_kernel(const float* __restrict__ src, __half* __restrict__ dst,
                             int K, int N) {
    __shared__ float t[32][33];
    int kb = blockIdx.y * 32, nb = blockIdx.x * 32;
    int tx = threadIdx.x, ty = threadIdx.y;   // 32 x 8
    #pragma unroll
    for (int i = 0; i < 4; i++)
        t[ty + i * 8][tx] = src[(size_t)(kb + ty + i * 8) * N + nb + tx];
    __syncthreads();
    #pragma unroll
    for (int i = 0; i < 4; i++)
        dst[(size_t)(nb + ty + i * 8) * K + kb + tx] = __float2half(t[tx][ty + i * 8]);
}

// straight convert fp32 -> fp16 (count % 4 == 0)
__global__ void conv_kernel(const float* __restrict__ src, __half* __restrict__ dst,
                            int n4) {
    int i = blockIdx.x * blockDim.x + threadIdx.x;
    if (i < n4) {
        float4 v = ((const float4*)src)[i];
        __half2* d = (__half2*)dst + i * 2;
        d[0] = __floats2half2_rn(v.x, v.y);
        d[1] = __floats2half2_rn(v.z, v.w);
    }
}

// ---------------- embedding ----------------
__global__ void embed_kernel(const int* __restrict__ idx,
                             const float* __restrict__ wte,
                             const float* __restrict__ wpe,
                             float* __restrict__ x) {
    int row = blockIdx.x;
    int t   = row % TSEQ;
    int tok = idx[row];
    const float* we = wte + (size_t)tok * DMODEL;
    const float* wp = wpe + (size_t)t   * DMODEL;
    float* xo = x + (size_t)row * DMODEL;
    for (int d = threadIdx.x; d < DMODEL; d += blockDim.x)
        xo[d] = we[d] + wp[d];
}

// ---------------- layernorm -> fp16 ----------------
__global__ void ln_kernel(const float* __restrict__ x,
                          const float* __restrict__ g,
                          const float* __restrict__ b,
                          __half* __restrict__ out) {
    int row = blockIdx.x;
    const float* xr = x + (size_t)row * DMODEL;
    __half* orow = out + (size_t)row * DMODEL;
    int tid = threadIdx.x;

    float s = 0.f, sq = 0.f;
    for (int d = tid; d < DMODEL; d += blockDim.x) {
        float v = xr[d];
        s += v; sq += v * v;
    }
    __shared__ float shs[256], shq[256];
    shs[tid] = s; shq[tid] = sq;
    __syncthreads();
    for (int o = 128; o > 0; o >>= 1) {
        if (tid < o) { shs[tid] += shs[tid + o]; shq[tid] += shq[tid + o]; }
        __syncthreads();
    }
    float mu  = shs[0] * (1.0f / DMODEL);
    float var = shq[0] * (1.0f / DMODEL) - mu * mu;
    float rs  = rsqrtf(var + LNEPS);
    for (int d = tid; d < DMODEL; d += blockDim.x)
        orow[d] = __float2half((xr[d] - mu) * rs * g[d] + b[d]);
}

// ---------------- fp16 tensor-core GEMM (m16n8k16, NT, cp.async 2-stage) ----
// C[M,N](ldc) = epi( A[M,K]h @ B[N,K]h^T ), K % 32 == 0, M % 128 == 0
#define GBM 128
#define GBN 128
#define GBK 32
#define KPAD 40   // halves per smem row (80B, 16B-aligned, odd*16B -> conflict-free frags)

__device__ __forceinline__ void cp16(uint32_t saddr, const void* g) {
    asm volatile("cp.async.cg.shared.global [%0], [%1], 16;" :: "r"(saddr), "l"(g));
}
__device__ __forceinline__ void cp16z(uint32_t saddr, const void* g, int srcsize) {
    asm volatile("cp.async.cg.shared.global [%0], [%1], 16, %2;"
                 :: "r"(saddr), "l"(g), "r"(srcsize));
}
__device__ __forceinline__ void mma_f16(float c[4], const uint32_t a[4],
                                        const uint32_t b[2]) {
    asm volatile(
        "mma.sync.aligned.m16n8k16.row.col.f32.f16.f16.f32 "
        "{%0,%1,%2,%3}, {%4,%5,%6,%7}, {%8,%9}, {%0,%1,%2,%3};"
        : "+f"(c[0]), "+f"(c[1]), "+f"(c[2]), "+f"(c[3])
        : "r"(a[0]), "r"(a[1]), "r"(a[2]), "r"(a[3]), "r"(b[0]), "r"(b[1]));
}
__device__ __forceinline__ float gelu_exact(float v) {
    return 0.5f * v * (1.0f + erff(v * 0.70710678118654752f));
}

template<typename OutT, bool BIAS, bool GELU, bool RES>
__global__ __launch_bounds__(256)
void hgemm(const __half* __restrict__ A, const __half* __restrict__ B,
           const float* __restrict__ bias, const float* __restrict__ res,
           OutT* __restrict__ C, int M, int N, int K, int ldc) {
    __shared__ __align__(16) __half As[2][GBM * KPAD];
    __shared__ __align__(16) __half Bs[2][GBN * KPAD];

    const int bm   = blockIdx.y * GBM;
    const int bn   = blockIdx.x * GBN;
    const int tid  = threadIdx.x;
    const int lane = tid & 31;
    const int wid  = tid >> 5;
    const int warpM = wid & 3;
    const int warpN = wid >> 2;
    const int grp  = lane >> 2;
    const int tig  = lane & 3;

    const uint32_t asBase = (uint32_t)__cvta_generic_to_shared(&As[0][0]);
    const uint32_t bsBase = (uint32_t)__cvta_generic_to_shared(&Bs[0][0]);

    float acc[2][8][4];
    #pragma unroll
    for (int mi = 0; mi < 2; mi++)
        #pragma unroll
        for (int ni = 0; ni < 8; ni++)
            #pragma unroll
            for (int r = 0; r < 4; r++) acc[mi][ni][r] = 0.f;

    const int row0 = tid >> 2;        // 0..63
    const int kq   = tid & 3;         // 16B chunk within 32-half row

    auto issue_tile = [&](int t, int s) {
        int kt = t * GBK;
        #pragma unroll
        for (int i = 0; i < 2; i++) {
            int row = row0 + i * 64;
            uint32_t sa = asBase + ((s * GBM + row) * KPAD + kq * 8) * 2;
            cp16(sa, A + (size_t)(bm + row) * K + kt + kq * 8);
            int n = bn + row;
            int nc = n < N ? n : 0;
            uint32_t sb = bsBase + ((s * GBN + row) * KPAD + kq * 8) * 2;
            cp16z(sb, B + (size_t)nc * K + kt + kq * 8, n < N ? 16 : 0);
        }
        asm volatile("cp.async.commit_group;");
    };

    const int ntiles = K / GBK;
    issue_tile(0, 0);

    for (int t = 0; t < ntiles; t++) {
        const int s = t & 1;
        if (t + 1 < ntiles) {
            issue_tile(t + 1, (t + 1) & 1);
            asm volatile("cp.async.wait_group 1;");
        } else {
            asm volatile("cp.async.wait_group 0;");
        }
        __syncthreads();

        const __half* as = &As[s][0];
        const __half* bs = &Bs[s][0];
        #pragma unroll
        for (int ks = 0; ks < 2; ks++) {
            uint32_t a[2][4];
            #pragma unroll
            for (int mi = 0; mi < 2; mi++) {
                int rm = warpM * 32 + mi * 16;
                const __half* pa = as + ks * 16 + tig * 2;
                a[mi][0] = *(const uint32_t*)(pa + (rm + grp)     * KPAD);
                a[mi][1] = *(const uint32_t*)(pa + (rm + grp + 8) * KPAD);
                a[mi][2] = *(const uint32_t*)(pa + (rm + grp)     * KPAD + 8);
                a[mi][3] = *(const uint32_t*)(pa + (rm + grp + 8) * KPAD + 8);
            }
            uint32_t b[8][2];
            #pragma unroll
            for (int ni = 0; ni < 8; ni++) {
                int cn = warpN * 64 + ni * 8 + grp;
                const __half* pb = bs + cn * KPAD + ks * 16 + tig * 2;
                b[ni][0] = *(const uint32_t*)(pb);
                b[ni][1] = *(const uint32_t*)(pb + 8);
            }
            #pragma unroll
            for (int mi = 0; mi < 2; mi++)
                #pragma unroll
                for (int ni = 0; ni < 8; ni++)
                    mma_f16(acc[mi][ni], a[mi], b[ni]);
        }
        __syncthreads();
    }

    // ---- epilogue ----
    #pragma unroll
    for (int mi = 0; mi < 2; mi++) {
        #pragma unroll
        for (int ni = 0; ni < 8; ni++) {
            int row0e = bm + warpM * 32 + mi * 16 + grp;
            int col0e = bn + warpN * 64 + ni * 8 + 2 * tig;
            #pragma unroll
            for (int r = 0; r < 4; r++) {
                int row = row0e + (r >= 2 ? 8 : 0);
                int col = col0e + (r & 1);
                if (col < N) {
                    float v = acc[mi][ni][r];
                    if (BIAS) v += bias[col];
                    if (GELU) v = gelu_exact(v);
                    if (RES)  v += res[(size_t)row * ldc + col];
                    if constexpr (sizeof(OutT) == 4)
                        C[(size_t)row * ldc + col] = v;
                    else
                        C[(size_t)row * ldc + col] = __float2half(v);
                }
            }
        }
    }
}

// ---------------- fused causal attention over fused qkv (fp16 in/out) -------
#define ATQ 16
#define ATK 32
__global__ __launch_bounds__(128)
void attn_kernel(const __half* __restrict__ qkv, __half* __restrict__ O) {
    int qb   = blockIdx.x * ATQ;
    int h    = blockIdx.y;
    int b    = blockIdx.z;
    int warp = threadIdx.x >> 5;
    int lane = threadIdx.x & 31;

    __shared__ float Ks[ATK][HDIM];
    __shared__ float Vs[ATK][HDIM];

    const size_t rbase = (size_t)b * TSEQ * QKVN + (size_t)h * HDIM;
    const __half* Qg = qkv + rbase;
    const __half* Kg = qkv + rbase + DMODEL;
    const __half* Vg = qkv + rbase + 2 * DMODEL;

    float qreg[4][2], m[4], l[4], acc[4][2];
    #pragma unroll
    for (int r = 0; r < 4; r++) {
        int qi = qb + warp * 4 + r;
        qreg[r][0] = __half2float(Qg[(size_t)qi * QKVN + lane]);
        qreg[r][1] = __half2float(Qg[(size_t)qi * QKVN + 32 + lane]);
        m[r] = -1e30f; l[r] = 0.f;
        acc[r][0] = 0.f; acc[r][1] = 0.f;
    }

    const int qmax = qb + ATQ - 1;
    for (int kt = 0; kt <= qmax; kt += ATK) {
        if (kt) __syncthreads();
        // 32 rows x 64 halves = 256 chunks of 8 halves
        for (int t = threadIdx.x; t < ATK * HDIM / 8; t += 128) {
            int row = t >> 3;
            int c8  = t & 7;
            uint4 kr = *(const uint4*)(Kg + (size_t)(kt + row) * QKVN + c8 * 8);
            uint4 vr = *(const uint4*)(Vg + (size_t)(kt + row) * QKVN + c8 * 8);
            const __half2* kh = (const __half2*)&kr;
            const __half2* vh = (const __half2*)&vr;
            #pragma unroll
            for (int j = 0; j < 4; j++) {
                float2 kf = __half22float2(kh[j]);
                float2 vf = __half22float2(vh[j]);
                Ks[row][c8 * 8 + j * 2]     = kf.x;
                Ks[row][c8 * 8 + j * 2 + 1] = kf.y;
                Vs[row][c8 * 8 + j * 2]     = vf.x;
                Vs[row][c8 * 8 + j * 2 + 1] = vf.y;
            }
        }
        __syncthreads();

        int kend = qmax - kt + 1;
        if (kend > ATK) kend = ATK;
        for (int kk = 0; kk < kend; kk++) {
            int ki = kt + kk;
            float k0 = Ks[kk][lane], k1 = Ks[kk][lane + 32];
            float v0 = Vs[kk][lane], v1 = Vs[kk][lane + 32];
            #pragma unroll
            for (int r = 0; r < 4; r++) {
                int qi = qb + warp * 4 + r;
                if (ki <= qi) {
                    float d = qreg[r][0] * k0 + qreg[r][1] * k1;
                    d += __shfl_xor_sync(0xffffffffu, d, 16);
                    d += __shfl_xor_sync(0xffffffffu, d, 8);
                    d += __shfl_xor_sync(0xffffffffu, d, 4);
                    d += __shfl_xor_sync(0xffffffffu, d, 2);
                    d += __shfl_xor_sync(0xffffffffu, d, 1);
                    float sv = d * 0.125f;
                    float nm = fmaxf(m[r], sv);
                    float cf = __expf(sv - nm);
                    float f  = __expf(m[r] - nm);
                    l[r] = l[r] * f + cf;
                    acc[r][0] = acc[r][0] * f + cf * v0;
                    acc[r][1] = acc[r][1] * f + cf * v1;
                    m[r] = nm;
                }
            }
        }
    }

    #pragma unroll
    for (int r = 0; r < 4; r++) {
        int qi = qb + warp * 4 + r;
        float inv = 1.0f / l[r];
        size_t ob = ((size_t)b * TSEQ + qi) * DMODEL + (size_t)h * HDIM;
        O[ob + lane]      = __float2half(acc[r][0] * inv);
        O[ob + 32 + lane] = __float2half(acc[r][1] * inv);
    }
}

// ---------------- orchestration ----------------
static inline dim3 ggrid(int M, int N) { return dim3((N + GBN - 1) / GBN, M / GBM); }

extern "C" void kernel_launch(void* const* d_in, const int* in_sizes, int n_in,
                              void* d_out, int out_size) {
    const int*   idx   = (const int*)  d_in[0];
    const float* wte   = (const float*)d_in[1];
    const float* wpe   = (const float*)d_in[2];
    const float* Wq    = (const float*)d_in[3];
    const float* Wk    = (const float*)d_in[4];
    const float* Wv    = (const float*)d_in[5];
    const float* Wo    = (const float*)d_in[6];
    const float* ln1_g = (const float*)d_in[7];
    const float* ln1_b = (const float*)d_in[8];
    const float* ln2_g = (const float*)d_in[9];
    const float* ln2_b = (const float*)d_in[10];
    const float* W1    = (const float*)d_in[11];
    const float* b1    = (const float*)d_in[12];
    const float* W2    = (const float*)d_in[13];
    const float* b2    = (const float*)d_in[14];
    const float* lnf_g = (const float*)d_in[15];
    const float* lnf_b = (const float*)d_in[16];
    float* out = (float*)d_out;

    float *x;
    __half *h16, *a16, *f16, *qkv, *wqkv, *wot, *w1t, *w2t, *wteh;
    cudaGetSymbolAddress((void**)&x,    g_x);
    cudaGetSymbolAddress((void**)&h16,  g_h16);
    cudaGetSymbolAddress((void**)&a16,  g_a16);
    cudaGetSymbolAddress((void**)&f16,  g_f16);
    cudaGetSymbolAddress((void**)&qkv,  g_qkv);
    cudaGetSymbolAddress((void**)&wqkv, g_wqkv);
    cudaGetSymbolAddress((void**)&wot,  g_wot);
    cudaGetSymbolAddress((void**)&w1t,  g_w1t);
    cudaGetSymbolAddress((void**)&w2t,  g_w2t);
    cudaGetSymbolAddress((void**)&wteh, g_wteh);

    // ---- weight conversion (transposed fp16) ----
    dim3 tb(32, 8);
    for (int l = 0; l < NLAYER; l++) {
        const size_t wo_off = (size_t)l * DMODEL * DMODEL;
        convT_kernel<<<dim3(DMODEL/32, DMODEL/32), tb>>>(
            Wq + wo_off, wqkv + (size_t)l * QKVN * DMODEL,               DMODEL, DMODEL);
        convT_kernel<<<dim3(DMODEL/32, DMODEL/32), tb>>>(
            Wk + wo_off, wqkv + (size_t)l * QKVN * DMODEL + (size_t)DMODEL*DMODEL,   DMODEL, DMODEL);
        convT_kernel<<<dim3(DMODEL/32, DMODEL/32), tb>>>(
            Wv + wo_off, wqkv + (size_t)l * QKVN * DMODEL + (size_t)2*DMODEL*DMODEL, DMODEL, DMODEL);
        convT_kernel<<<dim3(DMODEL/32, DMODEL/32), tb>>>(
            Wo + wo_off, wot + wo_off, DMODEL, DMODEL);
        convT_kernel<<<dim3(FFDIM/32, DMODEL/32), tb>>>(
            W1 + (size_t)l * DMODEL * FFDIM, w1t + (size_t)l * FFDIM * DMODEL, DMODEL, FFDIM);
        convT_kernel<<<dim3(DMODEL/32, FFDIM/32), tb>>>(
            W2 + (size_t)l * FFDIM * DMODEL, w2t + (size_t)l * DMODEL * FFDIM, FFDIM, DMODEL);
    }
    {
        int n4 = VOCAB * DMODEL / 4;
        conv_kernel<<<(n4 + 255) / 256, 256>>>(wte, wteh, n4);
    }

    embed_kernel<<<NROW, 256>>>(idx, wte, wpe, x);

    for (int l = 0; l < NLAYER; l++) {
        const __half* wqkv_l = wqkv + (size_t)l * QKVN * DMODEL;
        const __half* wo_l   = wot  + (size_t)l * DMODEL * DMODEL;
        const __half* w1_l   = w1t  + (size_t)l * FFDIM * DMODEL;
        const __half* w2_l   = w2t  + (size_t)l * DMODEL * FFDIM;
        const float*  bb1    = b1 + (size_t)l * FFDIM;
        const float*  bb2    = b2 + (size_t)l * DMODEL;

        ln_kernel<<<NROW, 256>>>(x, ln1_g + (size_t)l * DMODEL,
                                 ln1_b + (size_t)l * DMODEL, h16);

        // fused qkv: [4096,2304] fp16
        hgemm<__half, false, false, false><<<ggrid(NROW, QKVN), 256>>>(
            h16, wqkv_l, nullptr, nullptr, qkv, NROW, QKVN, DMODEL, QKVN);

        {
            dim3 g(TSEQ / ATQ, NHEAD, BATCH);
            attn_kernel<<<g, 128>>>(qkv, a16);
        }

        hgemm<float, false, false, true><<<ggrid(NROW, DMODEL), 256>>>(
            a16, wo_l, nullptr, x, x, NROW, DMODEL, DMODEL, DMODEL);

        ln_kernel<<<NROW, 256>>>(x, ln2_g + (size_t)l * DMODEL,
                                 ln2_b + (size_t)l * DMODEL, h16);

        hgemm<__half, true, true, false><<<ggrid(NROW, FFDIM), 256>>>(
            h16, w1_l, bb1, nullptr, f16, NROW, FFDIM, DMODEL, FFDIM);
        hgemm<float, true, false, true><<<ggrid(NROW, DMODEL), 256>>>(
            f16, w2_l, bb2, x, x, NROW, DMODEL, FFDIM, DMODEL);
    }

    ln_kernel<<<NROW, 256>>>(x, lnf_g, lnf_b, h16);
    hgemm<float, false, false, false><<<ggrid(NROW, VOCAB), 256>>>(
        h16, wteh, nullptr, nullptr, out, NROW, VOCAB, DMODEL, VOCAB);

    (void)in_sizes; (void)n_in; (void)out_size;
}

// round 7
// speedup vs baseline: 7.5529x; 4.2469x over previous
#include <cuda_runtime.h>
#include <cuda_fp16.h>
#include <math.h>
#include <stdint.h>

// ---------------- problem constants ----------------
#define BATCH 2
#define TSEQ  2048
#define NROW  (BATCH * TSEQ)   // 4096
#define DMODEL 768
#define NHEAD 12
#define HDIM  64
#define NLAYER 6
#define FFDIM (4 * DMODEL)     // 3072
#define QKVN  (3 * DMODEL)     // 2304
#define VOCAB 50257
#define LNEPS 1e-5f

// ---------------- scratch (device globals; no allocations) ----------------
__device__ float  g_x[NROW * DMODEL];          // residual stream (fp32)
__device__ __half g_h16[NROW * DMODEL];        // LN output (GEMM A)
__device__ __half g_a16[NROW * DMODEL];        // attention out (GEMM A)
__device__ __half g_f16[NROW * FFDIM];         // GELU out (GEMM A)
__device__ __half g_qkv[NROW * QKVN];          // fused qkv output

// fp16 transposed weights [N,K]
__device__ __half g_wqkv[NLAYER * QKVN * DMODEL];     // [2304,768] per layer
__device__ __half g_wot [NLAYER * DMODEL * DMODEL];   // [768,768]
__device__ __half g_w1t [NLAYER * FFDIM * DMODEL];    // [3072,768]
__device__ __half g_w2t [NLAYER * DMODEL * FFDIM];    // [768,3072]
__device__ __half g_wteh[VOCAB * DMODEL];             // [50257,768] (already NT)

// ---------------- weight conversion ----------------
// transpose+convert: src fp32 [K,N] row-major -> dst fp16 [N,K]
__global__ void convT_kernel(const float* __restrict__ src, __half* __restrict__ dst,
                             int K, int N) {
    __shared__ float t[32][33];
    int kb = blockIdx.y * 32, nb = blockIdx.x * 32;
    int tx = threadIdx.x, ty = threadIdx.y;   // 32 x 8
    #pragma unroll
    for (int i = 0; i < 4; i++)
        t[ty + i * 8][tx] = src[(size_t)(kb + ty + i * 8) * N + nb + tx];
    __syncthreads();
    #pragma unroll
    for (int i = 0; i < 4; i++)
        dst[(size_t)(nb + ty + i * 8) * K + kb + tx] = __float2half(t[tx][ty + i * 8]);
}

// straight convert fp32 -> fp16 (count % 4 == 0)
__global__ void conv_kernel(const float* __restrict__ src, __half* __restrict__ dst,
                            int n4) {
    int i = blockIdx.x * blockDim.x + threadIdx.x;
    if (i < n4) {
        float4 v = ((const float4*)src)[i];
        __half2* d = (__half2*)dst + i * 2;
        d[0] = __floats2half2_rn(v.x, v.y);
        d[1] = __floats2half2_rn(v.z, v.w);
    }
}

// ---------------- embedding ----------------
__global__ void embed_kernel(const int* __restrict__ idx,
                             const float* __restrict__ wte,
                             const float* __restrict__ wpe,
                             float* __restrict__ x) {
    int row = blockIdx.x;
    int t   = row % TSEQ;
    int tok = idx[row];
    const float* we = wte + (size_t)tok * DMODEL;
    const float* wp = wpe + (size_t)t   * DMODEL;
    float* xo = x + (size_t)row * DMODEL;
    for (int d = threadIdx.x; d < DMODEL; d += blockDim.x)
        xo[d] = we[d] + wp[d];
}

// ---------------- layernorm -> fp16 ----------------
__global__ void ln_kernel(const float* __restrict__ x,
                          const float* __restrict__ g,
                          const float* __restrict__ b,
                          __half* __restrict__ out) {
    int row = blockIdx.x;
    const float* xr = x + (size_t)row * DMODEL;
    __half* orow = out + (size_t)row * DMODEL;
    int tid = threadIdx.x;

    float s = 0.f, sq = 0.f;
    for (int d = tid; d < DMODEL; d += blockDim.x) {
        float v = xr[d];
        s += v; sq += v * v;
    }
    __shared__ float shs[256], shq[256];
    shs[tid] = s; shq[tid] = sq;
    __syncthreads();
    for (int o = 128; o > 0; o >>= 1) {
        if (tid < o) { shs[tid] += shs[tid + o]; shq[tid] += shq[tid + o]; }
        __syncthreads();
    }
    float mu  = shs[0] * (1.0f / DMODEL);
    float var = shq[0] * (1.0f / DMODEL) - mu * mu;
    float rs  = rsqrtf(var + LNEPS);
    for (int d = tid; d < DMODEL; d += blockDim.x)
        orow[d] = __float2half((xr[d] - mu) * rs * g[d] + b[d]);
}

// ---------------- fp16 tensor-core GEMM (m16n8k16, NT, cp.async 2-stage) ----
#define GBM 128
#define GBN 128
#define GBK 32
#define KPAD 40

__device__ __forceinline__ void cp16(uint32_t saddr, const void* g) {
    asm volatile("cp.async.cg.shared.global [%0], [%1], 16;" :: "r"(saddr), "l"(g));
}
__device__ __forceinline__ void cp16z(uint32_t saddr, const void* g, int srcsize) {
    asm volatile("cp.async.cg.shared.global [%0], [%1], 16, %2;"
                 :: "r"(saddr), "l"(g), "r"(srcsize));
}
__device__ __forceinline__ void mma_f16(float c[4], const uint32_t a[4],
                                        const uint32_t b[2]) {
    asm volatile(
        "mma.sync.aligned.m16n8k16.row.col.f32.f16.f16.f32 "
        "{%0,%1,%2,%3}, {%4,%5,%6,%7}, {%8,%9}, {%0,%1,%2,%3};"
        : "+f"(c[0]), "+f"(c[1]), "+f"(c[2]), "+f"(c[3])
        : "r"(a[0]), "r"(a[1]), "r"(a[2]), "r"(a[3]), "r"(b[0]), "r"(b[1]));
}
__device__ __forceinline__ float gelu_exact(float v) {
    return 0.5f * v * (1.0f + erff(v * 0.70710678118654752f));
}

template<typename OutT, bool BIAS, bool GELU, bool RES>
__global__ __launch_bounds__(256)
void hgemm(const __half* __restrict__ A, const __half* __restrict__ B,
           const float* __restrict__ bias, const float* __restrict__ res,
           OutT* __restrict__ C, int M, int N, int K, int ldc) {
    __shared__ __align__(16) __half As[2][GBM * KPAD];
    __shared__ __align__(16) __half Bs[2][GBN * KPAD];

    const int bm   = blockIdx.y * GBM;
    const int bn   = blockIdx.x * GBN;
    const int tid  = threadIdx.x;
    const int lane = tid & 31;
    const int wid  = tid >> 5;
    const int warpM = wid & 3;
    const int warpN = wid >> 2;
    const int grp  = lane >> 2;
    const int tig  = lane & 3;

    const uint32_t asBase = (uint32_t)__cvta_generic_to_shared(&As[0][0]);
    const uint32_t bsBase = (uint32_t)__cvta_generic_to_shared(&Bs[0][0]);

    float acc[2][8][4];
    #pragma unroll
    for (int mi = 0; mi < 2; mi++)
        #pragma unroll
        for (int ni = 0; ni < 8; ni++)
            #pragma unroll
            for (int r = 0; r < 4; r++) acc[mi][ni][r] = 0.f;

    const int row0 = tid >> 2;
    const int kq   = tid & 3;

    auto issue_tile = [&](int t, int s) {
        int kt = t * GBK;
        #pragma unroll
        for (int i = 0; i < 2; i++) {
            int row = row0 + i * 64;
            uint32_t sa = asBase + ((s * GBM + row) * KPAD + kq * 8) * 2;
            cp16(sa, A + (size_t)(bm + row) * K + kt + kq * 8);
            int n = bn + row;
            int nc = n < N ? n : 0;
            uint32_t sb = bsBase + ((s * GBN + row) * KPAD + kq * 8) * 2;
            cp16z(sb, B + (size_t)nc * K + kt + kq * 8, n < N ? 16 : 0);
        }
        asm volatile("cp.async.commit_group;");
    };

    const int ntiles = K / GBK;
    issue_tile(0, 0);

    for (int t = 0; t < ntiles; t++) {
        const int s = t & 1;
        if (t + 1 < ntiles) {
            issue_tile(t + 1, (t + 1) & 1);
            asm volatile("cp.async.wait_group 1;");
        } else {
            asm volatile("cp.async.wait_group 0;");
        }
        __syncthreads();

        const __half* as = &As[s][0];
        const __half* bs = &Bs[s][0];
        #pragma unroll
        for (int ks = 0; ks < 2; ks++) {
            uint32_t a[2][4];
            #pragma unroll
            for (int mi = 0; mi < 2; mi++) {
                int rm = warpM * 32 + mi * 16;
                const __half* pa = as + ks * 16 + tig * 2;
                a[mi][0] = *(const uint32_t*)(pa + (rm + grp)     * KPAD);
                a[mi][1] = *(const uint32_t*)(pa + (rm + grp + 8) * KPAD);
                a[mi][2] = *(const uint32_t*)(pa + (rm + grp)     * KPAD + 8);
                a[mi][3] = *(const uint32_t*)(pa + (rm + grp + 8) * KPAD + 8);
            }
            uint32_t b[8][2];
            #pragma unroll
            for (int ni = 0; ni < 8; ni++) {
                int cn = warpN * 64 + ni * 8 + grp;
                const __half* pb = bs + cn * KPAD + ks * 16 + tig * 2;
                b[ni][0] = *(const uint32_t*)(pb);
                b[ni][1] = *(const uint32_t*)(pb + 8);
            }
            #pragma unroll
            for (int mi = 0; mi < 2; mi++)
                #pragma unroll
                for (int ni = 0; ni < 8; ni++)
                    mma_f16(acc[mi][ni], a[mi], b[ni]);
        }
        __syncthreads();
    }

    #pragma unroll
    for (int mi = 0; mi < 2; mi++) {
        #pragma unroll
        for (int ni = 0; ni < 8; ni++) {
            int row0e = bm + warpM * 32 + mi * 16 + grp;
            int col0e = bn + warpN * 64 + ni * 8 + 2 * tig;
            #pragma unroll
            for (int r = 0; r < 4; r++) {
                int row = row0e + (r >= 2 ? 8 : 0);
                int col = col0e + (r & 1);
                if (col < N) {
                    float v = acc[mi][ni][r];
                    if (BIAS) v += bias[col];
                    if (GELU) v = gelu_exact(v);
                    if (RES)  v += res[(size_t)row * ldc + col];
                    if constexpr (sizeof(OutT) == 4)
                        C[(size_t)row * ldc + col] = v;
                    else
                        C[(size_t)row * ldc + col] = __float2half(v);
                }
            }
        }
    }
}

// ---------------- tensor-core flash attention (causal, fp16 MMA) -----------
// block: 128 threads (4 warps); each block: 64 query rows of one (b,h);
// each warp: 16 rows. K staged [key][hd], V staged transposed [hd][key].
#define FTQ 64
#define FTK 64
#define FKP 72   // smem row pad (halves): conflict-free fragment reads

__global__ __launch_bounds__(128)
void fattn_kernel(const __half* __restrict__ qkv, __half* __restrict__ O) {
    __shared__ __half Ks[FTK][FKP];
    __shared__ __half Vt[HDIM][FKP];

    const int tid  = threadIdx.x;
    const int w    = tid >> 5;
    const int lane = tid & 31;
    const int grp  = lane >> 2;
    const int tig  = lane & 3;
    const int qb   = blockIdx.x * FTQ;
    const int h    = blockIdx.y;
    const int b    = blockIdx.z;

    const size_t rbase = (size_t)b * TSEQ * QKVN + (size_t)h * HDIM;
    const __half* Qg = qkv + rbase;
    const __half* Kg = qkv + rbase + DMODEL;
    const __half* Vg = qkv + rbase + 2 * DMODEL;

    // Q fragments: warp rows qb + w*16 + {grp, grp+8}, k-slices of 16
    uint32_t qf[4][4];
    {
        const int r0 = qb + w * 16 + grp;
        const __half* q0 = Qg + (size_t)r0 * QKVN;
        const __half* q1 = Qg + (size_t)(r0 + 8) * QKVN;
        #pragma unroll
        for (int ks = 0; ks < 4; ks++) {
            qf[ks][0] = *(const uint32_t*)(q0 + ks * 16 + tig * 2);
            qf[ks][1] = *(const uint32_t*)(q1 + ks * 16 + tig * 2);
            qf[ks][2] = *(const uint32_t*)(q0 + ks * 16 + tig * 2 + 8);
            qf[ks][3] = *(const uint32_t*)(q1 + ks * 16 + tig * 2 + 8);
        }
    }

    const float SC = 0.125f * 1.4426950408889634f;  // (1/sqrt(64)) * log2(e)
    float m0 = -1e30f, m1 = -1e30f, l0 = 0.f, l1 = 0.f;
    float accO[8][4];
    #pragma unroll
    for (int ni = 0; ni < 8; ni++)
        #pragma unroll
        for (int r = 0; r < 4; r++) accO[ni][r] = 0.f;

    const int row0 = qb + w * 16 + grp;
    const int row1 = row0 + 8;
    const int ktiles = qb / FTK + 1;

    for (int t = 0; t < ktiles; t++) {
        const int kt = t * FTK;
        __syncthreads();
        // K tile: [key][hd], coalesced uint4
        for (int i = tid; i < FTK * HDIM / 8; i += 128) {
            int row = i >> 3, c8 = i & 7;
            *(uint4*)&Ks[row][c8 * 8] =
                *(const uint4*)(Kg + (size_t)(kt + row) * QKVN + c8 * 8);
        }
        // V tile transposed: [hd][key]; rp = i&31 -> conflict-free half2 stores
        for (int i = tid; i < 256; i += 128) {
            int rp = i & 31, c8 = i >> 5;   // rows 2rp,2rp+1; cols c8*8..+7
            uint4 v0 = *(const uint4*)(Vg + (size_t)(kt + 2 * rp)     * QKVN + c8 * 8);
            uint4 v1 = *(const uint4*)(Vg + (size_t)(kt + 2 * rp + 1) * QKVN + c8 * 8);
            const __half* h0 = (const __half*)&v0;
            const __half* h1 = (const __half*)&v1;
            #pragma unroll
            for (int j = 0; j < 8; j++) {
                __half2 p; p.x = h0[j]; p.y = h1[j];
                *(__half2*)&Vt[c8 * 8 + j][2 * rp] = p;
            }
        }
        __syncthreads();

        // S = Q K^T  (per warp: 16 x 64)
        float s[8][4];
        #pragma unroll
        for (int ni = 0; ni < 8; ni++) {
            s[ni][0] = 0.f; s[ni][1] = 0.f; s[ni][2] = 0.f; s[ni][3] = 0.f;
        }
        #pragma unroll
        for (int ks = 0; ks < 4; ks++) {
            #pragma unroll
            for (int ni = 0; ni < 8; ni++) {
                uint32_t bf[2];
                bf[0] = *(const uint32_t*)&Ks[ni * 8 + grp][ks * 16 + tig * 2];
                bf[1] = *(const uint32_t*)&Ks[ni * 8 + grp][ks * 16 + tig * 2 + 8];
                mma_f16(s[ni], qf[ks], bf);
            }
        }

        // scale (log2 domain) + causal mask
        #pragma unroll
        for (int ni = 0; ni < 8; ni++) {
            int c0 = kt + ni * 8 + tig * 2, c1 = c0 + 1;
            s[ni][0] = (c0 <= row0) ? s[ni][0] * SC : -1e30f;
            s[ni][1] = (c1 <= row0) ? s[ni][1] * SC : -1e30f;
            s[ni][2] = (c0 <= row1) ? s[ni][2] * SC : -1e30f;
            s[ni][3] = (c1 <= row1) ? s[ni][3] * SC : -1e30f;
        }

        // row max (across regs, then across the quad: lanes tig^1, tig^2)
        float tm0 = -1e30f, tm1 = -1e30f;
        #pragma unroll
        for (int ni = 0; ni < 8; ni++) {
            tm0 = fmaxf(tm0, fmaxf(s[ni][0], s[ni][1]));
            tm1 = fmaxf(tm1, fmaxf(s[ni][2], s[ni][3]));
        }
        tm0 = fmaxf(tm0, __shfl_xor_sync(0xffffffffu, tm0, 1));
        tm0 = fmaxf(tm0, __shfl_xor_sync(0xffffffffu, tm0, 2));
        tm1 = fmaxf(tm1, __shfl_xor_sync(0xffffffffu, tm1, 1));
        tm1 = fmaxf(tm1, __shfl_xor_sync(0xffffffffu, tm1, 2));

        float nm0 = fmaxf(m0, tm0), nm1 = fmaxf(m1, tm1);
        float f0 = exp2f(m0 - nm0), f1 = exp2f(m1 - nm1);
        m0 = nm0; m1 = nm1;

        // P = exp2(s - m); pack P directly into A fragments
        uint32_t pf[4][4];
        float ts0 = 0.f, ts1 = 0.f;
        #pragma unroll
        for (int ni = 0; ni < 8; ni++) {
            float p0 = exp2f(s[ni][0] - nm0);
            float p1 = exp2f(s[ni][1] - nm0);
            float p2 = exp2f(s[ni][2] - nm1);
            float p3 = exp2f(s[ni][3] - nm1);
            ts0 += p0 + p1; ts1 += p2 + p3;
            __half2 h01 = __floats2half2_rn(p0, p1);
            __half2 h23 = __floats2half2_rn(p2, p3);
            int ks = ni >> 1, o = (ni & 1) * 2;
            pf[ks][o]     = *(uint32_t*)&h01;   // row grp
            pf[ks][o + 1] = *(uint32_t*)&h23;   // row grp+8
        }
        ts0 += __shfl_xor_sync(0xffffffffu, ts0, 1);
        ts0 += __shfl_xor_sync(0xffffffffu, ts0, 2);
        ts1 += __shfl_xor_sync(0xffffffffu, ts1, 1);
        ts1 += __shfl_xor_sync(0xffffffffu, ts1, 2);
        l0 = l0 * f0 + ts0;
        l1 = l1 * f1 + ts1;

        // rescale O accumulators
        #pragma unroll
        for (int ni = 0; ni < 8; ni++) {
            accO[ni][0] *= f0; accO[ni][1] *= f0;
            accO[ni][2] *= f1; accO[ni][3] *= f1;
        }

        // O += P @ V   (B fragments from Vt[hd][key])
        #pragma unroll
        for (int ks = 0; ks < 4; ks++) {
            #pragma unroll
            for (int ni = 0; ni < 8; ni++) {
                uint32_t bf[2];
                bf[0] = *(const uint32_t*)&Vt[ni * 8 + grp][ks * 16 + tig * 2];
                bf[1] = *(const uint32_t*)&Vt[ni * 8 + grp][ks * 16 + tig * 2 + 8];
                mma_f16(accO[ni], pf[ks], bf);
            }
        }
    }

    // normalize + write out (fp16, [row][h*64 + hd])
    const float inv0 = 1.0f / l0, inv1 = 1.0f / l1;
    const size_t ob0 = ((size_t)b * TSEQ + row0) * DMODEL + (size_t)h * HDIM;
    const size_t ob1 = ((size_t)b * TSEQ + row1) * DMODEL + (size_t)h * HDIM;
    #pragma unroll
    for (int ni = 0; ni < 8; ni++) {
        int c = ni * 8 + 2 * tig;
        *(__half2*)&O[ob0 + c] = __floats2half2_rn(accO[ni][0] * inv0, accO[ni][1] * inv0);
        *(__half2*)&O[ob1 + c] = __floats2half2_rn(accO[ni][2] * inv1, accO[ni][3] * inv1);
    }
}

// ---------------- orchestration ----------------
static inline dim3 ggrid(int M, int N) { return dim3((N + GBN - 1) / GBN, M / GBM); }

extern "C" void kernel_launch(void* const* d_in, const int* in_sizes, int n_in,
                              void* d_out, int out_size) {
    const int*   idx   = (const int*)  d_in[0];
    const float* wte   = (const float*)d_in[1];
    const float* wpe   = (const float*)d_in[2];
    const float* Wq    = (const float*)d_in[3];
    const float* Wk    = (const float*)d_in[4];
    const float* Wv    = (const float*)d_in[5];
    const float* Wo    = (const float*)d_in[6];
    const float* ln1_g = (const float*)d_in[7];
    const float* ln1_b = (const float*)d_in[8];
    const float* ln2_g = (const float*)d_in[9];
    const float* ln2_b = (const float*)d_in[10];
    const float* W1    = (const float*)d_in[11];
    const float* b1    = (const float*)d_in[12];
    const float* W2    = (const float*)d_in[13];
    const float* b2    = (const float*)d_in[14];
    const float* lnf_g = (const float*)d_in[15];
    const float* lnf_b = (const float*)d_in[16];
    float* out = (float*)d_out;

    float *x;
    __half *h16, *a16, *f16, *qkv, *wqkv, *wot, *w1t, *w2t, *wteh;
    cudaGetSymbolAddress((void**)&x,    g_x);
    cudaGetSymbolAddress((void**)&h16,  g_h16);
    cudaGetSymbolAddress((void**)&a16,  g_a16);
    cudaGetSymbolAddress((void**)&f16,  g_f16);
    cudaGetSymbolAddress((void**)&qkv,  g_qkv);
    cudaGetSymbolAddress((void**)&wqkv, g_wqkv);
    cudaGetSymbolAddress((void**)&wot,  g_wot);
    cudaGetSymbolAddress((void**)&w1t,  g_w1t);
    cudaGetSymbolAddress((void**)&w2t,  g_w2t);
    cudaGetSymbolAddress((void**)&wteh, g_wteh);

    // ---- weight conversion (transposed fp16) ----
    dim3 tb(32, 8);
    for (int l = 0; l < NLAYER; l++) {
        const size_t wo_off = (size_t)l * DMODEL * DMODEL;
        convT_kernel<<<dim3(DMODEL/32, DMODEL/32), tb>>>(
            Wq + wo_off, wqkv + (size_t)l * QKVN * DMODEL,               DMODEL, DMODEL);
        convT_kernel<<<dim3(DMODEL/32, DMODEL/32), tb>>>(
            Wk + wo_off, wqkv + (size_t)l * QKVN * DMODEL + (size_t)DMODEL*DMODEL,   DMODEL, DMODEL);
        convT_kernel<<<dim3(DMODEL/32, DMODEL/32), tb>>>(
            Wv + wo_off, wqkv + (size_t)l * QKVN * DMODEL + (size_t)2*DMODEL*DMODEL, DMODEL, DMODEL);
        convT_kernel<<<dim3(DMODEL/32, DMODEL/32), tb>>>(
            Wo + wo_off, wot + wo_off, DMODEL, DMODEL);
        convT_kernel<<<dim3(FFDIM/32, DMODEL/32), tb>>>(
            W1 + (size_t)l * DMODEL * FFDIM, w1t + (size_t)l * FFDIM * DMODEL, DMODEL, FFDIM);
        convT_kernel<<<dim3(DMODEL/32, FFDIM/32), tb>>>(
            W2 + (size_t)l * FFDIM * DMODEL, w2t + (size_t)l * DMODEL * FFDIM, FFDIM, DMODEL);
    }
    {
        int n4 = VOCAB * DMODEL / 4;
        conv_kernel<<<(n4 + 255) / 256, 256>>>(wte, wteh, n4);
    }

    embed_kernel<<<NROW, 256>>>(idx, wte, wpe, x);

    for (int l = 0; l < NLAYER; l++) {
        const __half* wqkv_l = wqkv + (size_t)l * QKVN * DMODEL;
        const __half* wo_l   = wot  + (size_t)l * DMODEL * DMODEL;
        const __half* w1_l   = w1t  + (size_t)l * FFDIM * DMODEL;
        const __half* w2_l   = w2t  + (size_t)l * DMODEL * FFDIM;
        const float*  bb1    = b1 + (size_t)l * FFDIM;
        const float*  bb2    = b2 + (size_t)l * DMODEL;

        ln_kernel<<<NROW, 256>>>(x, ln1_g + (size_t)l * DMODEL,
                                 ln1_b + (size_t)l * DMODEL, h16);

        hgemm<__half, false, false, false><<<ggrid(NROW, QKVN), 256>>>(
            h16, wqkv_l, nullptr, nullptr, qkv, NROW, QKVN, DMODEL, QKVN);

        {
            dim3 g(TSEQ / FTQ, NHEAD, BATCH);
            fattn_kernel<<<g, 128>>>(qkv, a16);
        }

        hgemm<float, false, false, true><<<ggrid(NROW, DMODEL), 256>>>(
            a16, wo_l, nullptr, x, x, NROW, DMODEL, DMODEL, DMODEL);

        ln_kernel<<<NROW, 256>>>(x, ln2_g + (size_t)l * DMODEL,
                                 ln2_b + (size_t)l * DMODEL, h16);

        hgemm<__half, true, true, false><<<ggrid(NROW, FFDIM), 256>>>(
            h16, w1_l, bb1, nullptr, f16, NROW, FFDIM, DMODEL, FFDIM);
        hgemm<float, true, false, true><<<ggrid(NROW, DMODEL), 256>>>(
            f16, w2_l, bb2, x, x, NROW, DMODEL, FFDIM, DMODEL);
    }

    ln_kernel<<<NROW, 256>>>(x, lnf_g, lnf_b, h16);
    hgemm<float, false, false, false><<<ggrid(NROW, VOCAB), 256>>>(
        h16, wteh, nullptr, nullptr, out, NROW, VOCAB, DMODEL, VOCAB);

    (void)in_sizes; (void)n_in; (void)out_size;
}